// round 3
// baseline (speedup 1.0000x reference)
#include <cuda_runtime.h>
#include <math.h>

// Problem constants (fixed shapes from reference setup_inputs)
#define N_ROWS 131072
#define D 64
#define K 512
#define TILE_M 128
#define PAD 68                      // 64 + 4 pad -> conflict-free LDS.128 across tx
#define NBLOCKS (N_ROWS / TILE_M)   // 1024

// Output layout: [xn | xn | proto | cvae | pdl]
#define XN2_OFF   ((long)N_ROWS * D)
#define PROTO_OFF (2L * N_ROWS * D)
#define CVAE_OFF  (PROTO_OFF + (long)N_ROWS * K)
#define PDL_OFF   (CVAE_OFF + 1)

// Scratch (no allocations allowed -> device globals)
__device__ unsigned int g_colmin[K];        // min of z per column, as positive-float bits
__device__ float        g_row_partial[NBLOCKS];
__device__ float        g_b2[K];

// ---------------------------------------------------------------------------
// Init: per-prototype squared norms + reset column mins
// ---------------------------------------------------------------------------
__global__ void swav_init_kernel(const float* __restrict__ W) {
    int k = blockIdx.x * blockDim.x + threadIdx.x;
    if (k < K) {
        float s = 0.f;
        #pragma unroll
        for (int d = 0; d < D; ++d) { float v = W[k * D + d]; s = fmaf(v, v, s); }
        g_b2[k] = s;
        g_colmin[k] = 0x7F800000u;  // +inf
    }
}

// ---------------------------------------------------------------------------
// Main: normalize 128 rows, write xn twice, GEMM vs all 512 prototypes,
// write proto, track row/col mins of z = a2 + b2 - 2*dot (sqrt deferred).
// ---------------------------------------------------------------------------
__global__ __launch_bounds__(256, 1)
void swav_main_kernel(const float* __restrict__ x, float* __restrict__ out) {
    extern __shared__ float sm[];
    float* As  = sm;                         // TILE_M * PAD
    float* Ws  = As + TILE_M * PAD;          // K * PAD
    float* a2s = Ws + K * PAD;               // TILE_M
    float* b2s = a2s + TILE_M;               // K
    unsigned int* cmin_s = (unsigned int*)(b2s + K);     // TILE_M (reused as float red)
    unsigned int* rmin_s = cmin_s + TILE_M;              // TILE_M

    const int t   = threadIdx.x;
    const int bid = blockIdx.x;
    const long row0 = (long)bid * TILE_M;

    // --- load x tile (coalesced float4) into padded smem ---
    const float4* xg = (const float4*)(x + row0 * D);
    for (int i = t; i < TILE_M * (D / 4); i += 256) {
        int r = i >> 4, d4 = i & 15;
        *(float4*)&As[r * PAD + d4 * 4] = xg[i];
    }
    // --- load full W into padded smem (stays hot in L2 chip-wide) ---
    {
        // W lives at g_b2? No: W comes via constant global pointer; pass through b2 path:
    }
    // b2 from global scratch
    for (int i = t; i < K; i += 256) b2s[i] = g_b2[i];
    if (t < TILE_M) rmin_s[t] = 0x7F800000u;
    __syncthreads();

    // --- normalize rows (threads 0..127, one row each) ---
    if (t < TILE_M) {
        float s = 0.f;
        #pragma unroll
        for (int d = 0; d < D; ++d) { float v = As[t * PAD + d]; s = fmaf(v, v, s); }
        float inv = 1.0f / fmaxf(sqrtf(s), 1e-12f);
        float a2 = 0.f;
        #pragma unroll
        for (int d = 0; d < D; ++d) {
            float v = As[t * PAD + d] * inv;
            As[t * PAD + d] = v;
            a2 = fmaf(v, v, a2);
        }
        a2s[t] = a2;
    }
    __syncthreads();

    // --- write xn (two copies, coalesced) ---
    {
        float4* xn1 = (float4*)(out + row0 * D);
        float4* xn2 = (float4*)(out + XN2_OFF + row0 * D);
        for (int i = t; i < TILE_M * (D / 4); i += 256) {
            int r = i >> 4, d4 = i & 15;
            float4 v = *(float4*)&As[r * PAD + d4 * 4];
            xn1[i] = v;
            xn2[i] = v;
        }
    }

    const int tx = t & 15, ty = t >> 4;
    float rmin[8];
    #pragma unroll
    for (int i = 0; i < 8; ++i) rmin[i] = 3.0e38f;
    float a2r[8];
    #pragma unroll
    for (int i = 0; i < 8; ++i) a2r[i] = a2s[ty * 8 + i];

    float* proto = out + PROTO_OFF + row0 * (long)K;

    for (int c = 0; c < 4; ++c) {
        if (t < TILE_M) cmin_s[t] = 0x7F800000u;
        __syncthreads();

        float acc[8][8];
        #pragma unroll
        for (int i = 0; i < 8; ++i)
            #pragma unroll
            for (int j = 0; j < 8; ++j) acc[i][j] = 0.f;

        const float* Abase = As + (ty * 8) * PAD;
        const float* Bbase = Ws + (c * 128 + tx * 8) * PAD;

        #pragma unroll
        for (int d4 = 0; d4 < 16; ++d4) {
            float4 a4[8], b4[8];
            #pragma unroll
            for (int i = 0; i < 8; ++i) a4[i] = *(const float4*)&Abase[i * PAD + d4 * 4];
            #pragma unroll
            for (int j = 0; j < 8; ++j) b4[j] = *(const float4*)&Bbase[j * PAD + d4 * 4];
            #pragma unroll
            for (int i = 0; i < 8; ++i)
                #pragma unroll
                for (int j = 0; j < 8; ++j) {
                    acc[i][j] = fmaf(a4[i].x, b4[j].x, acc[i][j]);
                    acc[i][j] = fmaf(a4[i].y, b4[j].y, acc[i][j]);
                    acc[i][j] = fmaf(a4[i].z, b4[j].z, acc[i][j]);
                    acc[i][j] = fmaf(a4[i].w, b4[j].w, acc[i][j]);
                }
        }

        float b2r[8];
        #pragma unroll
        for (int j = 0; j < 8; ++j) b2r[j] = b2s[c * 128 + tx * 8 + j];
        float cmin[8];
        #pragma unroll
        for (int j = 0; j < 8; ++j) cmin[j] = 3.0e38f;

        #pragma unroll
        for (int i = 0; i < 8; ++i) {
            float* prow = proto + (long)(ty * 8 + i) * K + c * 128 + tx * 8;
            *(float4*)&prow[0] = make_float4(acc[i][0], acc[i][1], acc[i][2], acc[i][3]);
            *(float4*)&prow[4] = make_float4(acc[i][4], acc[i][5], acc[i][6], acc[i][7]);
            #pragma unroll
            for (int j = 0; j < 8; ++j) {
                float z = fmaf(-2.f, acc[i][j], a2r[i] + b2r[j]);
                z = fmaxf(z, 0.f);                 // keep int-min trick valid
                rmin[i] = fminf(rmin[i], z);
                cmin[j] = fminf(cmin[j], z);
            }
        }

        #pragma unroll
        for (int j = 0; j < 8; ++j)
            atomicMin(&cmin_s[tx * 8 + j], __float_as_uint(cmin[j]));
        __syncthreads();
        if (t < TILE_M)
            atomicMin(&g_colmin[c * 128 + t], cmin_s[t]);
        // cmin_s[t] re-init next iter is by the same thread t -> no extra sync needed
    }

    // --- row-min reduce across tx, then block sum of sqrt ---
    #pragma unroll
    for (int i = 0; i < 8; ++i)
        atomicMin(&rmin_s[ty * 8 + i], __float_as_uint(rmin[i]));
    __syncthreads();

    float* red = (float*)cmin_s;  // reuse
    if (t < TILE_M)
        red[t] = sqrtf(fmaxf(__uint_as_float(rmin_s[t]), 1e-12f));
    __syncthreads();
    for (int s = 64; s > 0; s >>= 1) {
        if (t < s) red[t] += red[t + s];
        __syncthreads();
    }
    if (t == 0) g_row_partial[bid] = red[0];
}

// W-tile loader folded into main kernel requires W pointer; use a second copy of
// the main kernel signature instead: we pass W via a separate cooperative load.
// (Implemented as a wrapper: swav_main_kernel2 includes the W load.)
__global__ __launch_bounds__(256, 1)
void swav_gemm_kernel(const float* __restrict__ x, const float* __restrict__ W,
                      float* __restrict__ out) {
    extern __shared__ float sm[];
    float* Ws = sm + TILE_M * PAD;
    const float4* wg = (const float4*)W;
    for (int i = threadIdx.x; i < K * (D / 4); i += 256) {
        int r = i >> 4, d4 = i & 15;
        *(float4*)&Ws[r * PAD + d4 * 4] = wg[i];
    }
    // fallthrough into the same body via function-style reuse is not possible;
    // this kernel is unused. See launch: W load is inside swav_main2 below.
}

// Single real main kernel including the W load (the two above kept minimal).
__global__ __launch_bounds__(256, 1)
void swav_main2(const float* __restrict__ x, const float* __restrict__ W,
                float* __restrict__ out) {
    extern __shared__ float sm[];
    float* As  = sm;
    float* Ws  = As + TILE_M * PAD;
    float* a2s = Ws + K * PAD;
    float* b2s = a2s + TILE_M;
    unsigned int* cmin_s = (unsigned int*)(b2s + K);
    unsigned int* rmin_s = cmin_s + TILE_M;

    const int t   = threadIdx.x;
    const int bid = blockIdx.x;
    const long row0 = (long)bid * TILE_M;

    const float4* xg = (const float4*)(x + row0 * D);
    for (int i = t; i < TILE_M * (D / 4); i += 256) {
        int r = i >> 4, d4 = i & 15;
        *(float4*)&As[r * PAD + d4 * 4] = xg[i];
    }
    const float4* wg = (const float4*)W;
    for (int i = t; i < K * (D / 4); i += 256) {
        int r = i >> 4, d4 = i & 15;
        *(float4*)&Ws[r * PAD + d4 * 4] = wg[i];
    }
    for (int i = t; i < K; i += 256) b2s[i] = g_b2[i];
    if (t < TILE_M) rmin_s[t] = 0x7F800000u;
    __syncthreads();

    if (t < TILE_M) {
        float s = 0.f;
        #pragma unroll
        for (int d = 0; d < D; ++d) { float v = As[t * PAD + d]; s = fmaf(v, v, s); }
        float inv = 1.0f / fmaxf(sqrtf(s), 1e-12f);
        float a2 = 0.f;
        #pragma unroll
        for (int d = 0; d < D; ++d) {
            float v = As[t * PAD + d] * inv;
            As[t * PAD + d] = v;
            a2 = fmaf(v, v, a2);
        }
        a2s[t] = a2;
    }
    __syncthreads();

    {
        float4* xn1 = (float4*)(out + row0 * D);
        float4* xn2 = (float4*)(out + XN2_OFF + row0 * D);
        for (int i = t; i < TILE_M * (D / 4); i += 256) {
            int r = i >> 4, d4 = i & 15;
            float4 v = *(float4*)&As[r * PAD + d4 * 4];
            xn1[i] = v;
            xn2[i] = v;
        }
    }

    const int tx = t & 15, ty = t >> 4;
    float rmin[8];
    #pragma unroll
    for (int i = 0; i < 8; ++i) rmin[i] = 3.0e38f;
    float a2r[8];
    #pragma unroll
    for (int i = 0; i < 8; ++i) a2r[i] = a2s[ty * 8 + i];

    float* proto = out + PROTO_OFF + row0 * (long)K;

    for (int c = 0; c < 4; ++c) {
        if (t < TILE_M) cmin_s[t] = 0x7F800000u;
        __syncthreads();

        float acc[8][8];
        #pragma unroll
        for (int i = 0; i < 8; ++i)
            #pragma unroll
            for (int j = 0; j < 8; ++j) acc[i][j] = 0.f;

        const float* Abase = As + (ty * 8) * PAD;
        const float* Bbase = Ws + (c * 128 + tx * 8) * PAD;

        #pragma unroll
        for (int d4 = 0; d4 < 16; ++d4) {
            float4 a4[8], b4[8];
            #pragma unroll
            for (int i = 0; i < 8; ++i) a4[i] = *(const float4*)&Abase[i * PAD + d4 * 4];
            #pragma unroll
            for (int j = 0; j < 8; ++j) b4[j] = *(const float4*)&Bbase[j * PAD + d4 * 4];
            #pragma unroll
            for (int i = 0; i < 8; ++i)
                #pragma unroll
                for (int j = 0; j < 8; ++j) {
                    acc[i][j] = fmaf(a4[i].x, b4[j].x, acc[i][j]);
                    acc[i][j] = fmaf(a4[i].y, b4[j].y, acc[i][j]);
                    acc[i][j] = fmaf(a4[i].z, b4[j].z, acc[i][j]);
                    acc[i][j] = fmaf(a4[i].w, b4[j].w, acc[i][j]);
                }
        }

        float b2r[8];
        #pragma unroll
        for (int j = 0; j < 8; ++j) b2r[j] = b2s[c * 128 + tx * 8 + j];
        float cmin[8];
        #pragma unroll
        for (int j = 0; j < 8; ++j) cmin[j] = 3.0e38f;

        #pragma unroll
        for (int i = 0; i < 8; ++i) {
            float* prow = proto + (long)(ty * 8 + i) * K + c * 128 + tx * 8;
            *(float4*)&prow[0] = make_float4(acc[i][0], acc[i][1], acc[i][2], acc[i][3]);
            *(float4*)&prow[4] = make_float4(acc[i][4], acc[i][5], acc[i][6], acc[i][7]);
            #pragma unroll
            for (int j = 0; j < 8; ++j) {
                float z = fmaf(-2.f, acc[i][j], a2r[i] + b2r[j]);
                z = fmaxf(z, 0.f);
                rmin[i] = fminf(rmin[i], z);
                cmin[j] = fminf(cmin[j], z);
            }
        }

        #pragma unroll
        for (int j = 0; j < 8; ++j)
            atomicMin(&cmin_s[tx * 8 + j], __float_as_uint(cmin[j]));
        __syncthreads();
        if (t < TILE_M)
            atomicMin(&g_colmin[c * 128 + t], cmin_s[t]);
    }

    #pragma unroll
    for (int i = 0; i < 8; ++i)
        atomicMin(&rmin_s[ty * 8 + i], __float_as_uint(rmin[i]));
    __syncthreads();

    float* red = (float*)cmin_s;
    if (t < TILE_M)
        red[t] = sqrtf(fmaxf(__uint_as_float(rmin_s[t]), 1e-12f));
    __syncthreads();
    for (int s = 64; s > 0; s >>= 1) {
        if (t < s) red[t] += red[t + s];
        __syncthreads();
    }
    if (t == 0) g_row_partial[bid] = red[0];
}

// ---------------------------------------------------------------------------
// Final: deterministic reductions + scalar outputs
// ---------------------------------------------------------------------------
__global__ void swav_final_kernel(const float* __restrict__ recon,
                                  const float* __restrict__ kl,
                                  const float* __restrict__ mmd,
                                  float* __restrict__ out) {
    __shared__ float red[K];
    int t = threadIdx.x;  // K = 512 threads
    float s = 0.f;
    for (int i = t; i < NBLOCKS; i += K) s += g_row_partial[i];
    red[t] = s;
    __syncthreads();
    for (int st = 256; st > 0; st >>= 1) { if (t < st) red[t] += red[t + st]; __syncthreads(); }
    float rowsum = red[0];
    __syncthreads();

    red[t] = sqrtf(fmaxf(__uint_as_float(g_colmin[t]), 1e-12f));
    __syncthreads();
    for (int st = 256; st > 0; st >>= 1) { if (t < st) red[t] += red[t + st]; __syncthreads(); }

    if (t == 0) {
        float pdl = 0.5f * (rowsum / (float)N_ROWS) + 0.5f * (red[0] / (float)K);
        out[CVAE_OFF] = recon[0] + 0.5f * kl[0] + mmd[0];
        out[PDL_OFF]  = pdl;
    }
}

// ---------------------------------------------------------------------------
extern "C" void kernel_launch(void* const* d_in, const int* in_sizes, int n_in,
                              void* d_out, int out_size) {
    const float* x     = (const float*)d_in[0];
    const float* W     = (const float*)d_in[1];
    const float* recon = (const float*)d_in[2];
    const float* kl    = (const float*)d_in[3];
    const float* mmd   = (const float*)d_in[4];
    float* out = (float*)d_out;

    size_t smem = (size_t)(TILE_M * PAD + K * PAD + TILE_M + K + TILE_M + TILE_M) * sizeof(float);
    cudaFuncSetAttribute(swav_main2, cudaFuncAttributeMaxDynamicSharedMemorySize, (int)smem);

    swav_init_kernel<<<1, K>>>(W);
    swav_main2<<<NBLOCKS, 256, smem>>>(x, W, out);
    swav_final_kernel<<<1, K>>>(recon, kl, mmd, out);
}

// round 5
// speedup vs baseline: 3.0538x; 3.0538x over previous
#include <cuda_runtime.h>
#include <cuda_bf16.h>
#include <math.h>
#include <stdint.h>

// ---------------------------------------------------------------------------
// Problem constants
// ---------------------------------------------------------------------------
#define N_ROWS 131072
#define D 64
#define K 512
#define TILE_M 128
#define NBLOCKS (N_ROWS / TILE_M)   // 1024
#define PADB 144                    // bf16 tile row stride in BYTES (64*2 + 16)

// Output layout: [xn | xn | proto | cvae | pdl]
#define XN2_OFF   ((long)N_ROWS * D)
#define PROTO_OFF (2L * N_ROWS * D)
#define CVAE_OFF  (PROTO_OFF + (long)N_ROWS * K)
#define PDL_OFF   (CVAE_OFF + 1)

// Shared memory layout (bytes)
#define OFF_AHI   0                  // bf16 [128] rows x PADB
#define OFF_ALO   18432
#define OFF_WHI   36864              // bf16 [512] rows x PADB
#define OFF_WLO   110592
#define OFF_B2    184320             // f32 [512]
#define OFF_A2    186368             // f32 [128]
#define OFF_CMIN  186880             // u32 [512]
#define OFF_RMIN  188928             // u32 [128]
#define OFF_RED   189440             // f32 [128]
#define SMEM_TOTAL 189952

// Device scratch (no allocations allowed)
__device__ unsigned int g_colmin[K];
__device__ float        g_row_partial[NBLOCKS];
__device__ float        g_b2[K];
__device__ unsigned int g_Whi_img[K * 32];   // packed bf16x2 [512][32]
__device__ unsigned int g_Wlo_img[K * 32];

// ---------------------------------------------------------------------------
// Helpers (sm_80-level PTX only: ldmatrix + mma.sync — no tcgen05)
// ---------------------------------------------------------------------------
__device__ __forceinline__ uint32_t smem_u32(const void* p) {
    uint32_t a;
    asm("{ .reg .u64 t; cvta.to.shared.u64 t, %1; cvt.u32.u64 %0, t; }" : "=r"(a) : "l"(p));
    return a;
}
__device__ __forceinline__ void ldsm_x4(uint32_t* r, uint32_t addr) {
    asm volatile("ldmatrix.sync.aligned.m8n8.x4.shared.b16 {%0,%1,%2,%3}, [%4];"
                 : "=r"(r[0]), "=r"(r[1]), "=r"(r[2]), "=r"(r[3]) : "r"(addr));
}
__device__ __forceinline__ void mma_bf16(float* d, const uint32_t* a, uint32_t b0, uint32_t b1) {
    asm volatile("mma.sync.aligned.m16n8k16.row.col.f32.bf16.bf16.f32 "
                 "{%0,%1,%2,%3}, {%4,%5,%6,%7}, {%8,%9}, {%0,%1,%2,%3};"
                 : "+f"(d[0]), "+f"(d[1]), "+f"(d[2]), "+f"(d[3])
                 : "r"(a[0]), "r"(a[1]), "r"(a[2]), "r"(a[3]), "r"(b0), "r"(b1));
}

// ---------------------------------------------------------------------------
// Init: W -> packed bf16 hi/lo images + b2 + colmin reset. 512 warps.
// ---------------------------------------------------------------------------
__global__ void swav_init_kernel(const float* __restrict__ W) {
    int gt  = blockIdx.x * blockDim.x + threadIdx.x;
    int r   = gt >> 5;
    int lid = gt & 31;
    if (r >= K) return;

    float2 v = *(const float2*)&W[r * D + lid * 2];
    __nv_bfloat16 h0 = __float2bfloat16(v.x);
    __nv_bfloat16 h1 = __float2bfloat16(v.y);
    float l0 = v.x - __bfloat162float(h0);
    float l1 = v.y - __bfloat162float(h1);
    __nv_bfloat162 hp = __nv_bfloat162(h0, h1);
    __nv_bfloat162 lp = __nv_bfloat162(__float2bfloat16(l0), __float2bfloat16(l1));

    g_Whi_img[r * 32 + lid] = *(unsigned int*)&hp;
    g_Wlo_img[r * 32 + lid] = *(unsigned int*)&lp;

    float s = fmaf(v.x, v.x, v.y * v.y);
    #pragma unroll
    for (int o = 16; o > 0; o >>= 1) s += __shfl_xor_sync(0xffffffffu, s, o);
    if (lid == 0) { g_b2[r] = s; g_colmin[r] = 0x7F800000u; }
}

// ---------------------------------------------------------------------------
// Main: per CTA 128 rows x all 512 prototypes.
// normalize (regs) -> xn x2 -> bf16 hi/lo smem tiles -> HMMA split GEMM
// (2 col-halves, 128 accum regs) -> register epilogue (proto + z-mins).
// ---------------------------------------------------------------------------
__global__ __launch_bounds__(256, 1)
void swav_main_kernel(const float* __restrict__ x, float* __restrict__ out) {
    extern __shared__ __align__(16) char sm[];
    float*        b2s    = (float*)(sm + OFF_B2);
    float*        a2s    = (float*)(sm + OFF_A2);
    unsigned int* cmin_s = (unsigned int*)(sm + OFF_CMIN);
    unsigned int* rmin_s = (unsigned int*)(sm + OFF_RMIN);
    float*        red    = (float*)(sm + OFF_RED);

    const uint32_t sb  = smem_u32(sm);
    const int t   = threadIdx.x;
    const int lid = t & 31;
    const int wid = t >> 5;
    const long row0 = (long)blockIdx.x * TILE_M;

    // ---- Phase 1: W images -> padded smem tiles; init reductions ----
    {
        const uint4* whi = (const uint4*)g_Whi_img;   // [512*8] uint4
        const uint4* wlo = (const uint4*)g_Wlo_img;
        #pragma unroll
        for (int i = 0; i < 16; ++i) {
            int idx = t + i * 256;            // 4096 uint4
            int r = idx >> 3, c = idx & 7;
            *(uint4*)(sm + OFF_WHI + r * PADB + c * 16) = whi[idx];
            *(uint4*)(sm + OFF_WLO + r * PADB + c * 16) = wlo[idx];
        }
    }
    for (int i = t; i < K; i += 256) { b2s[i] = g_b2[i]; cmin_s[i] = 0x7F800000u; }
    if (t < TILE_M) rmin_s[t] = 0x7F800000u;

    // ---- Phase 2: load x, normalize in registers, write xn x2, build A tiles ----
    {
        const float4* xg  = (const float4*)(x + row0 * D);
        float4* xn1 = (float4*)(out + row0 * D);
        float4* xn2 = (float4*)(out + XN2_OFF + row0 * D);
        float4 v[8]; float s[8];
        #pragma unroll
        for (int i = 0; i < 8; ++i) {
            int idx = t + i * 256;                    // [128 rows][16 float4]
            v[i] = xg[idx];
            s[i] = fmaf(v[i].x, v[i].x, fmaf(v[i].y, v[i].y,
                    fmaf(v[i].z, v[i].z, v[i].w * v[i].w)));
        }
        #pragma unroll
        for (int m = 1; m < 16; m <<= 1)
            #pragma unroll
            for (int i = 0; i < 8; ++i)
                s[i] += __shfl_xor_sync(0xffffffffu, s[i], m);
        #pragma unroll
        for (int i = 0; i < 8; ++i) {
            int idx = t + i * 256;
            int r = idx >> 4, c = idx & 15;
            float inv = 1.0f / fmaxf(sqrtf(s[i]), 1e-12f);
            float4 w4 = make_float4(v[i].x * inv, v[i].y * inv, v[i].z * inv, v[i].w * inv);
            xn1[idx] = w4;
            xn2[idx] = w4;
            if ((t & 15) == 0) a2s[r] = s[i] * inv * inv;

            __nv_bfloat16 hx = __float2bfloat16(w4.x), hy = __float2bfloat16(w4.y);
            __nv_bfloat16 hz = __float2bfloat16(w4.z), hw = __float2bfloat16(w4.w);
            __nv_bfloat162 hp0 = __nv_bfloat162(hx, hy);
            __nv_bfloat162 hp1 = __nv_bfloat162(hz, hw);
            __nv_bfloat162 lp0 = __nv_bfloat162(__float2bfloat16(w4.x - __bfloat162float(hx)),
                                                __float2bfloat16(w4.y - __bfloat162float(hy)));
            __nv_bfloat162 lp1 = __nv_bfloat162(__float2bfloat16(w4.z - __bfloat162float(hz)),
                                                __float2bfloat16(w4.w - __bfloat162float(hw)));
            uint2 hh = make_uint2(*(unsigned*)&hp0, *(unsigned*)&hp1);
            uint2 ll = make_uint2(*(unsigned*)&lp0, *(unsigned*)&lp1);
            *(uint2*)(sm + OFF_AHI + r * PADB + c * 8) = hh;
            *(uint2*)(sm + OFF_ALO + r * PADB + c * 8) = ll;
        }
    }
    __syncthreads();

    // ---- Phase 3: HMMA split GEMM + epilogue, two column halves ----
    const int wy = wid & 3, wx = wid >> 2;
    const int m0 = wy * 32;

    // ldmatrix lane addressing
    const uint32_t a_off  = (uint32_t)(m0 + (lid & 15)) * PADB + ((lid >> 4) * 16);
    const uint32_t aaddr_hi = sb + OFF_AHI + a_off;
    const uint32_t aaddr_lo = sb + OFF_ALO + a_off;
    const uint32_t b_rowi = ((lid >> 4) << 3) + (lid & 7);
    const uint32_t b_koff = ((lid >> 3) & 1) * 16;

    float a2r[2][2];
    #pragma unroll
    for (int mf = 0; mf < 2; ++mf) {
        a2r[mf][0] = a2s[m0 + mf * 16 + (lid >> 2)];
        a2r[mf][1] = a2s[m0 + mf * 16 + (lid >> 2) + 8];
    }

    float rowmin[4];
    #pragma unroll
    for (int j = 0; j < 4; ++j) rowmin[j] = 3.0e38f;

    for (int h = 0; h < 2; ++h) {
        const int nb = h * 256 + wx * 128;
        float acc[2][16][4];
        #pragma unroll
        for (int mf = 0; mf < 2; ++mf)
            #pragma unroll
            for (int p = 0; p < 16; ++p)
                #pragma unroll
                for (int q = 0; q < 4; ++q) acc[mf][p][q] = 0.f;

        #pragma unroll 1
        for (int k = 0; k < 4; ++k) {
            const uint32_t ka = (uint32_t)k * 32;
            uint32_t ah[2][4], al[2][4];
            ldsm_x4(ah[0], aaddr_hi + ka);
            ldsm_x4(ah[1], aaddr_hi + 16 * PADB + ka);
            ldsm_x4(al[0], aaddr_lo + ka);
            ldsm_x4(al[1], aaddr_lo + 16 * PADB + ka);
            #pragma unroll
            for (int p = 0; p < 8; ++p) {
                uint32_t baddr = sb + OFF_WHI +
                    (uint32_t)(nb + p * 16 + b_rowi) * PADB + b_koff + ka;
                uint32_t bh[4], bl[4];
                ldsm_x4(bh, baddr);
                ldsm_x4(bl, baddr + (OFF_WLO - OFF_WHI));
                #pragma unroll
                for (int mf = 0; mf < 2; ++mf) {
                    mma_bf16(acc[mf][2 * p],     ah[mf], bh[0], bh[1]);
                    mma_bf16(acc[mf][2 * p],     ah[mf], bl[0], bl[1]);
                    mma_bf16(acc[mf][2 * p],     al[mf], bh[0], bh[1]);
                    mma_bf16(acc[mf][2 * p + 1], ah[mf], bh[2], bh[3]);
                    mma_bf16(acc[mf][2 * p + 1], ah[mf], bl[2], bl[3]);
                    mma_bf16(acc[mf][2 * p + 1], al[mf], bh[2], bh[3]);
                }
            }
        }

        // Epilogue: proto stores + z-mins, all from registers
        #pragma unroll
        for (int p = 0; p < 16; ++p) {
            const int c = nb + p * 8 + 2 * (lid & 3);
            const float b2c0 = b2s[c], b2c1 = b2s[c + 1];
            float cm0 = 3.0e38f, cm1 = 3.0e38f;
            #pragma unroll
            for (int mf = 0; mf < 2; ++mf) {
                float* d = acc[mf][p];
                const int r0 = m0 + mf * 16 + (lid >> 2);
                *(float2*)(out + PROTO_OFF + (row0 + r0) * (long)K + c)
                    = make_float2(d[0], d[1]);
                *(float2*)(out + PROTO_OFF + (row0 + r0 + 8) * (long)K + c)
                    = make_float2(d[2], d[3]);
                float z0 = fmaxf(fmaf(-2.f, d[0], a2r[mf][0] + b2c0), 0.f);
                float z1 = fmaxf(fmaf(-2.f, d[1], a2r[mf][0] + b2c1), 0.f);
                float z2 = fmaxf(fmaf(-2.f, d[2], a2r[mf][1] + b2c0), 0.f);
                float z3 = fmaxf(fmaf(-2.f, d[3], a2r[mf][1] + b2c1), 0.f);
                rowmin[mf * 2]     = fminf(rowmin[mf * 2],     fminf(z0, z1));
                rowmin[mf * 2 + 1] = fminf(rowmin[mf * 2 + 1], fminf(z2, z3));
                cm0 = fminf(cm0, fminf(z0, z2));
                cm1 = fminf(cm1, fminf(z1, z3));
            }
            #pragma unroll
            for (int o = 4; o < 32; o <<= 1) {
                cm0 = fminf(cm0, __shfl_xor_sync(0xffffffffu, cm0, o));
                cm1 = fminf(cm1, __shfl_xor_sync(0xffffffffu, cm1, o));
            }
            if (lid < 4) {
                atomicMin(&cmin_s[c],     __float_as_uint(cm0));
                atomicMin(&cmin_s[c + 1], __float_as_uint(cm1));
            }
        }
    }

    // Row-min: reduce across the 4 lanes of each quad, then smem atomics
    #pragma unroll
    for (int o = 1; o < 4; o <<= 1)
        #pragma unroll
        for (int j = 0; j < 4; ++j)
            rowmin[j] = fminf(rowmin[j], __shfl_xor_sync(0xffffffffu, rowmin[j], o));
    if ((lid & 3) == 0) {
        const int rq = lid >> 2;
        atomicMin(&rmin_s[m0 + rq],      __float_as_uint(rowmin[0]));
        atomicMin(&rmin_s[m0 + rq + 8],  __float_as_uint(rowmin[1]));
        atomicMin(&rmin_s[m0 + 16 + rq], __float_as_uint(rowmin[2]));
        atomicMin(&rmin_s[m0 + 24 + rq], __float_as_uint(rowmin[3]));
    }
    __syncthreads();

    // ---- Phase 4: block reductions -> global scratch ----
    if (t < TILE_M)
        red[t] = sqrtf(fmaxf(__uint_as_float(rmin_s[t]), 1e-12f));
    __syncthreads();
    for (int s = 64; s > 0; s >>= 1) {
        if (t < s) red[t] += red[t + s];
        __syncthreads();
    }
    if (t == 0) g_row_partial[blockIdx.x] = red[0];
    atomicMin(&g_colmin[t],       cmin_s[t]);
    atomicMin(&g_colmin[t + 256], cmin_s[t + 256]);
}

// ---------------------------------------------------------------------------
// Final: deterministic reductions + scalar outputs
// ---------------------------------------------------------------------------
__global__ void swav_final_kernel(const float* __restrict__ recon,
                                  const float* __restrict__ kl,
                                  const float* __restrict__ mmd,
                                  float* __restrict__ out) {
    __shared__ float red[K];
    int t = threadIdx.x;  // 512 threads
    float s = 0.f;
    for (int i = t; i < NBLOCKS; i += K) s += g_row_partial[i];
    red[t] = s;
    __syncthreads();
    for (int st = 256; st > 0; st >>= 1) { if (t < st) red[t] += red[t + st]; __syncthreads(); }
    float rowsum = red[0];
    __syncthreads();

    red[t] = sqrtf(fmaxf(__uint_as_float(g_colmin[t]), 1e-12f));
    __syncthreads();
    for (int st = 256; st > 0; st >>= 1) { if (t < st) red[t] += red[t + st]; __syncthreads(); }

    if (t == 0) {
        float pdl = 0.5f * (rowsum / (float)N_ROWS) + 0.5f * (red[0] / (float)K);
        out[CVAE_OFF] = recon[0] + 0.5f * kl[0] + mmd[0];
        out[PDL_OFF]  = pdl;
    }
}

// ---------------------------------------------------------------------------
extern "C" void kernel_launch(void* const* d_in, const int* in_sizes, int n_in,
                              void* d_out, int out_size) {
    const float* x     = (const float*)d_in[0];
    const float* W     = (const float*)d_in[1];
    const float* recon = (const float*)d_in[2];
    const float* kl    = (const float*)d_in[3];
    const float* mmd   = (const float*)d_in[4];
    float* out = (float*)d_out;

    cudaFuncSetAttribute(swav_main_kernel,
                         cudaFuncAttributeMaxDynamicSharedMemorySize, SMEM_TOTAL);

    swav_init_kernel<<<64, 256>>>(W);
    swav_main_kernel<<<NBLOCKS, 256, SMEM_TOTAL>>>(x, out);
    swav_final_kernel<<<1, K>>>(recon, kl, mmd, out);
}